// round 8
// baseline (speedup 1.0000x reference)
#include <cuda_runtime.h>

// TSModel: 2-layer LSTM (layer0: 1->64, layer1: 64->1; layer1 input = c0,
// output = c1). B=2048, T=1024, fp32.
//
// R6: fused unit-owner layout. 147 CTAs x 288 threads, MROWS=14, 1 CTA/SM.
//  - threads 0..255: unit u = tid&63, row-group q = tid>>6 (rows q, q+4, q+8, q+12).
//    Each thread owns ALL 4 gate rows of its unit (128 packed-f32x2 weight regs),
//    computes gates -> activations -> c,h locally. c stays in registers.
//  - ONE __syncthreads per step (Hs/Cs double-buffered; no Gs round-trip).
//  - warp 8 (threads 256..287): layer-1 + output, pipelined 1 step behind,
//    hidden under the gate warps' FMA stream.

#define BATCH 2048
#define TSTEPS 1024
#define UNITS 64
#define MROWS 14
#define NCTA ((BATCH + MROWS - 1) / MROWS)   // 147
#define NTHR 288
#define CSTRIDE 66                            // pad: conflict-free layer-1 reads

typedef unsigned long long u64;

__device__ __forceinline__ u64 pack2(float lo, float hi) {
    u64 r;
    asm("mov.b64 %0, {%1, %2};" : "=l"(r) : "f"(lo), "f"(hi));
    return r;
}
__device__ __forceinline__ void unpack2(u64 v, float& lo, float& hi) {
    asm("mov.b64 {%0, %1}, %2;" : "=f"(lo), "=f"(hi) : "l"(v));
}
__device__ __forceinline__ u64 fma2(u64 a, u64 b, u64 c) {
    u64 d;
    asm("fma.rn.f32x2 %0, %1, %2, %3;" : "=l"(d) : "l"(a), "l"(b), "l"(c));
    return d;
}
__device__ __forceinline__ float rcp_apx(float x) {
    float r;
    asm("rcp.approx.f32 %0, %1;" : "=f"(r) : "f"(x));
    return r;
}
// sigmoid(x) = 1 / (1 + e^-x)
__device__ __forceinline__ float sig_f(float x) {
    return rcp_apx(1.0f + __expf(-x));
}
// tanh(x) = 1 - 2/(1 + e^{2x})
__device__ __forceinline__ float tanh_f(float x) {
    return fmaf(-2.0f, rcp_apx(1.0f + __expf(x + x)), 1.0f);
}

__global__ void __launch_bounds__(NTHR, 1)
lstm_kernel(const float* __restrict__ in,
            const float* __restrict__ Wih0, const float* __restrict__ Whh0,
            const float* __restrict__ bih0, const float* __restrict__ bhh0,
            const float* __restrict__ Wih1, const float* __restrict__ Whh1,
            const float* __restrict__ bih1, const float* __restrict__ bhh1,
            float* __restrict__ out) {
    __shared__ __align__(16) float Hs[2][MROWS][UNITS];      // h double-buffer
    __shared__ __align__(16) float Cs[2][MROWS][CSTRIDE];    // c copy for layer-1
    __shared__ __align__(16) float W1s[4][UNITS];            // Wih1 staged

    const int tid = threadIdx.x;
    const int r0 = blockIdx.x * MROWS;
    const int mrows = min(MROWS, BATCH - r0);

    // ---- per-thread persistent state (scoped wide; used under role guards) ----
    u64 w[4][32];                 // gate-thread: W_hh0 rows {u,u+64,u+128,u+192}
    float wx[4], bs[4];           // gate-thread: x-weights + fused biases
    float creg[4] = {0.f, 0.f, 0.f, 0.f};   // gate-thread: c per owned row
    float xcur[4] = {0.f, 0.f, 0.f, 0.f};
    float xnxt[4] = {0.f, 0.f, 0.f, 0.f};
    const int u = tid & 63;
    const int q = tid >> 6;       // 0..3 for gate threads

    // layer-1 warp state
    const int lane = tid - 256;               // valid when tid >= 256
    const int r_raw = (lane >= 0) ? (lane >> 1) : 0;
    const int gp = (lane >= 0) ? ((lane & 1) * 2) : 0;
    const int rC = min(r_raw, mrows - 1);     // clamped (avoid OOB smem reads)
    float h1r = 0.f, c1r = 0.f;
    float wh1[4], bb1[4];
#pragma unroll
    for (int g = 0; g < 4; g++) {
        wh1[g] = Whh1[g];
        bb1[g] = bih1[g] + bhh1[g];
    }

    if (tid < 256) {
#pragma unroll
        for (int g = 0; g < 4; g++) {
            const int row = g * 64 + u;
            const float2* wr = (const float2*)(Whh0 + row * UNITS);
#pragma unroll
            for (int k = 0; k < 32; k++) {
                float2 v = wr[k];
                w[g][k] = pack2(v.x, v.y);
            }
            wx[g] = Wih0[row];
            bs[g] = bih0[row] + bhh0[row];
        }
        // prefetch x for t=0
#pragma unroll
        for (int j = 0; j < 4; j++) {
            const int m = q + 4 * j;
            xcur[j] = (m < mrows) ? in[(size_t)(r0 + m) * TSTEPS] : 0.f;
        }
    }

    // zero Hs, stage W1s
    for (int i = tid; i < 2 * MROWS * UNITS; i += NTHR) (&Hs[0][0][0])[i] = 0.f;
    for (int i = tid; i < 4 * UNITS; i += NTHR) (&W1s[0][0])[i] = Wih1[i];
    __syncthreads();

    // ---- unified time loop: gate threads do step `it`, layer-1 does `it-1` ----
    for (int it = 0; it <= TSTEPS; it++) {
        if (tid < 256) {
            if (it < TSTEPS) {
                const int rb = it & 1;        // read h buffer
                const int wb = rb ^ 1;        // write h buffer
                // prefetch next x
#pragma unroll
                for (int j = 0; j < 4; j++) {
                    const int m = q + 4 * j;
                    xnxt[j] = (m < mrows && it + 1 < TSTEPS)
                                  ? in[(size_t)(r0 + m) * TSTEPS + it + 1] : 0.f;
                }
#pragma unroll
                for (int j = 0; j < 4; j++) {
                    const int m = q + 4 * j;
                    if (m < mrows) {
                        u64 ax0 = pack2(fmaf(xcur[j], wx[0], bs[0]), 0.f), ay0 = 0ULL;
                        u64 ax1 = pack2(fmaf(xcur[j], wx[1], bs[1]), 0.f), ay1 = 0ULL;
                        u64 ax2 = pack2(fmaf(xcur[j], wx[2], bs[2]), 0.f), ay2 = 0ULL;
                        u64 ax3 = pack2(fmaf(xcur[j], wx[3], bs[3]), 0.f), ay3 = 0ULL;
                        const ulonglong2* hp = (const ulonglong2*)&Hs[rb][m][0];
#pragma unroll
                        for (int k2 = 0; k2 < 16; k2++) {
                            ulonglong2 hv = hp[k2];   // LDS.128 broadcast -> 8 FMA2
                            ax0 = fma2(w[0][2 * k2], hv.x, ax0);
                            ay0 = fma2(w[0][2 * k2 + 1], hv.y, ay0);
                            ax1 = fma2(w[1][2 * k2], hv.x, ax1);
                            ay1 = fma2(w[1][2 * k2 + 1], hv.y, ay1);
                            ax2 = fma2(w[2][2 * k2], hv.x, ax2);
                            ay2 = fma2(w[2][2 * k2 + 1], hv.y, ay2);
                            ax3 = fma2(w[3][2 * k2], hv.x, ax3);
                            ay3 = fma2(w[3][2 * k2 + 1], hv.y, ay3);
                        }
                        float a, b, c, d;
                        unpack2(ax0, a, b); unpack2(ay0, c, d);
                        const float gi = (a + b) + (c + d);
                        unpack2(ax1, a, b); unpack2(ay1, c, d);
                        const float gf = (a + b) + (c + d);
                        unpack2(ax2, a, b); unpack2(ay2, c, d);
                        const float gg = (a + b) + (c + d);
                        unpack2(ax3, a, b); unpack2(ay3, c, d);
                        const float go = (a + b) + (c + d);
                        const float cn = sig_f(gf) * creg[j] + sig_f(gi) * tanh_f(gg);
                        const float hn = sig_f(go) * tanh_f(cn);
                        creg[j] = cn;
                        Hs[wb][m][u] = hn;
                        Cs[rb][m][u] = cn;    // layer-1 reads this next iter
                    }
                }
#pragma unroll
                for (int j = 0; j < 4; j++) xcur[j] = xnxt[j];
            }
        } else {
            if (it >= 1) {
                const int tc = it - 1;
                const int rbc = tc & 1;
                u64 accA = 0ULL, accB = 0ULL;
                const u64* cp = (const u64*)&Cs[rbc][rC][0];
                const u64* wA = (const u64*)&W1s[gp][0];
                const u64* wB = (const u64*)&W1s[gp + 1][0];
#pragma unroll
                for (int k2 = 0; k2 < 32; k2++) {
                    u64 cv = cp[k2];
                    accA = fma2(wA[k2], cv, accA);
                    accB = fma2(wB[k2], cv, accB);
                }
                float a, b;
                unpack2(accA, a, b);
                const float dotA = a + b;
                unpack2(accB, a, b);
                const float dotB = a + b;
                const float oA = __shfl_xor_sync(0xffffffffu, dotA, 1);
                const float oB = __shfl_xor_sync(0xffffffffu, dotB, 1);
                const bool hi2 = (lane & 1) != 0;
                const float d0 = hi2 ? oA : dotA;
                const float d1 = hi2 ? oB : dotB;
                const float d2 = hi2 ? dotA : oA;
                const float d3 = hi2 ? dotB : oB;
                const float gi = fmaf(wh1[0], h1r, d0 + bb1[0]);
                const float gf = fmaf(wh1[1], h1r, d1 + bb1[1]);
                const float gg = fmaf(wh1[2], h1r, d2 + bb1[2]);
                const float go = fmaf(wh1[3], h1r, d3 + bb1[3]);
                c1r = sig_f(gf) * c1r + sig_f(gi) * tanh_f(gg);
                h1r = sig_f(go) * tanh_f(c1r);
                if (r_raw < mrows && !hi2)
                    out[(size_t)(r0 + r_raw) * TSTEPS + tc] = c1r;
            }
        }
        __syncthreads();
    }
}

extern "C" void kernel_launch(void* const* d_in, const int* in_sizes, int n_in,
                              void* d_out, int out_size) {
    (void)in_sizes; (void)n_in; (void)out_size;
    lstm_kernel<<<NCTA, NTHR>>>(
        (const float*)d_in[0],  // input (2048,1024)
        (const float*)d_in[1],  // W_ih0 (256,1)
        (const float*)d_in[2],  // W_hh0 (256,64)
        (const float*)d_in[3],  // b_ih0 (256)
        (const float*)d_in[4],  // b_hh0 (256)
        (const float*)d_in[5],  // W_ih1 (4,64)
        (const float*)d_in[6],  // W_hh1 (4,1)
        (const float*)d_in[7],  // b_ih1 (4)
        (const float*)d_in[8],  // b_hh1 (4)
        (float*)d_out);         // out (2048,1024)
}

// round 10
// speedup vs baseline: 2.9685x; 2.9685x over previous
#include <cuda_runtime.h>

// TSModel: 2-layer LSTM (layer0: 1->64, layer1: 64->1; layer1 input = c0,
// per-step output = c1). B=2048, T=1024, fp32.
//
// R9: warp-local gate grouping, ONE __syncthreads per step.
//  - 293 CTAs x 256 threads, MROWS=7, 2 CTAs/SM (regs capped like R0).
//  - warp w owns units [8w, 8w+8); lane l = (unit 8w+(l>>2), gate l&3).
//    Thread owns one W_hh0 row in 32 packed-f32x2 regs (64 regs).
//  - Phase A (gates) -> Gs -> __syncwarp -> Phase B (activations, c in regs,
//    h to double-buffered Hs) -> __syncthreads. Gate->unit handoff is
//    warp-local, so the old mid-step CTA barrier is gone.
//  - Layer-1 runs pipelined one step behind at the top of each iteration
//    (warps 0..6, reading double-buffered Cs) — off the critical path.

#define BATCH 2048
#define TSTEPS 1024
#define UNITS 64
#define MROWS 7
#define NCTA ((BATCH + MROWS - 1) / MROWS)   // 293
#define NTHR 256

typedef unsigned long long u64;

__device__ __forceinline__ u64 pack2(float lo, float hi) {
    u64 r;
    asm("mov.b64 %0, {%1, %2};" : "=l"(r) : "f"(lo), "f"(hi));
    return r;
}
__device__ __forceinline__ void unpack2(u64 v, float& lo, float& hi) {
    asm("mov.b64 {%0, %1}, %2;" : "=f"(lo), "=f"(hi) : "l"(v));
}
__device__ __forceinline__ u64 fma2(u64 a, u64 b, u64 c) {
    u64 d;
    asm("fma.rn.f32x2 %0, %1, %2, %3;" : "=l"(d) : "l"(a), "l"(b), "l"(c));
    return d;
}
__device__ __forceinline__ float rcp_apx(float x) {
    float r;
    asm("rcp.approx.f32 %0, %1;" : "=f"(r) : "f"(x));
    return r;
}
// sigmoid(x) = 1 / (1 + e^-x)
__device__ __forceinline__ float sig_f(float x) {
    return rcp_apx(1.0f + __expf(-x));
}
// tanh(x) = 1 - 2/(1 + e^{2x})
__device__ __forceinline__ float tanh_f(float x) {
    return fmaf(-2.0f, rcp_apx(1.0f + __expf(x + x)), 1.0f);
}

__global__ void __launch_bounds__(NTHR, 2)
lstm_kernel(const float* __restrict__ in,
            const float* __restrict__ Wih0, const float* __restrict__ Whh0,
            const float* __restrict__ bih0, const float* __restrict__ bhh0,
            const float* __restrict__ Wih1, const float* __restrict__ Whh1,
            const float* __restrict__ bih1, const float* __restrict__ bhh1,
            float* __restrict__ out) {
    __shared__ __align__(16) float Hs[2][MROWS][UNITS];      // h double-buffer
    __shared__ __align__(16) float Cs[2][MROWS][UNITS];      // c for layer-1
    __shared__ __align__(16) float Gs[MROWS][UNITS][4];      // gates (warp-local)
    __shared__ __align__(16) float Xs[MROWS][TSTEPS];

    const int tid = threadIdx.x;
    const int lane = tid & 31;
    const int wid = tid >> 5;                 // 0..7
    const int r0 = blockIdx.x * MROWS;
    const int mrows = min(MROWS, BATCH - r0);

    // ---- gate-thread identity: unit u, gate g; weight row = g*64 + u ----
    const int u = 8 * wid + (lane >> 2);
    const int g = lane & 3;
    const int row = g * UNITS + u;

    u64 w[32];
    {
        const float2* wr = (const float2*)(Whh0 + row * UNITS);
#pragma unroll
        for (int k = 0; k < 32; k++) {
            float2 v = wr[k];
            w[k] = pack2(v.x, v.y);
        }
    }
    const float wx = Wih0[row];
    const float bsum = bih0[row] + bhh0[row];

    // ---- Phase-B identity: tasks lane and lane+32 over (m, unit_local) ----
    const int m0 = lane >> 3;                 // 0..3
    const int m1 = m0 + 4;                    // 4..6 (lane<24)
    const int ub = 8 * wid + (lane & 7);      // unit for activation tasks
    float creg0 = 0.0f, creg1 = 0.0f;

    // ---- Layer-1 identity (R0 Phase-C style): warp wid handles batch row wid
    const int g1i = lane & 3;
    const int s1 = lane >> 2;
    float wi1[8];
#pragma unroll
    for (int k = 0; k < 8; k++) wi1[k] = Wih1[g1i * UNITS + s1 + 8 * k];
    const float whh1g = Whh1[g1i];
    const float b1g = bih1[g1i] + bhh1[g1i];
    float h1 = 0.0f, c1 = 0.0f;

    // Stage input rows into SMEM (coalesced float4 copy)
    {
        const float4* src = (const float4*)(in + (size_t)r0 * TSTEPS);
        float4* dst = (float4*)&Xs[0][0];
        const int n4 = mrows * (TSTEPS / 4);
        for (int i = tid; i < n4; i += NTHR) dst[i] = src[i];
    }
    // Zero both h buffers
    for (int i = tid; i < 2 * MROWS * UNITS; i += NTHR) (&Hs[0][0][0])[i] = 0.0f;
    __syncthreads();

    // ---- time loop: one __syncthreads per step ----
    for (int it = 0; it < TSTEPS; it++) {
        const int rb = it & 1;
        const int wb = rb ^ 1;

        // Layer-1 for step it-1 (pipelined; Cs[(it-1)&1] ordered by last barrier)
        if (it > 0 && wid < mrows) {
            const int pb = (it - 1) & 1;
            float acc = 0.0f;
#pragma unroll
            for (int k = 0; k < 8; k++)
                acc = fmaf(wi1[k], Cs[pb][wid][s1 + 8 * k], acc);
            acc += __shfl_xor_sync(0xffffffffu, acc, 4);
            acc += __shfl_xor_sync(0xffffffffu, acc, 8);
            acc += __shfl_xor_sync(0xffffffffu, acc, 16);
            acc += fmaf(whh1g, h1, b1g);
            const float gi = __shfl_sync(0xffffffffu, acc, 0);
            const float gf = __shfl_sync(0xffffffffu, acc, 1);
            const float gg = __shfl_sync(0xffffffffu, acc, 2);
            const float go = __shfl_sync(0xffffffffu, acc, 3);
            c1 = sig_f(gf) * c1 + sig_f(gi) * tanh_f(gg);
            h1 = sig_f(go) * tanh_f(c1);
            if (lane == 0) out[(size_t)(r0 + wid) * TSTEPS + (it - 1)] = c1;
        }

        // Phase A: gate dot products for all rows (one gate row per thread)
#pragma unroll
        for (int m = 0; m < MROWS; m++) {
            if (m < mrows) {
                const float xv = Xs[m][it];
                u64 ax = pack2(fmaf(xv, wx, bsum), 0.0f);
                u64 ay = 0ULL;
                const ulonglong2* hp = (const ulonglong2*)&Hs[rb][m][0];
#pragma unroll
                for (int k = 0; k < 16; k++) {
                    ulonglong2 hv = hp[k];    // LDS.128 broadcast
                    ax = fma2(w[2 * k], hv.x, ax);
                    ay = fma2(w[2 * k + 1], hv.y, ay);
                }
                float a, b, c, d;
                unpack2(ax, a, b);
                unpack2(ay, c, d);
                Gs[m][u][g] = (a + b) + (c + d);
            }
        }
        __syncwarp();

        // Phase B: activations for this warp's 8 units x mrows (warp-local Gs)
        {
            // task 0: (m0, ub) — m0 in 0..3, always < mrows (mrows >= 4)
            const float4 gv = *(const float4*)&Gs[m0][ub][0];
            const float cn = sig_f(gv.y) * creg0 + sig_f(gv.x) * tanh_f(gv.z);
            const float hn = sig_f(gv.w) * tanh_f(cn);
            creg0 = cn;
            Hs[wb][m0][ub] = hn;
            Cs[rb][m0][ub] = cn;
            // task 1: (m1, ub) — valid when lane<24 and m1<mrows
            if (lane < 24 && m1 < mrows) {
                const float4 gw = *(const float4*)&Gs[m1][ub][0];
                const float cn1 = sig_f(gw.y) * creg1 + sig_f(gw.x) * tanh_f(gw.z);
                const float hn1 = sig_f(gw.w) * tanh_f(cn1);
                creg1 = cn1;
                Hs[wb][m1][ub] = hn1;
                Cs[rb][m1][ub] = cn1;
            }
        }
        __syncthreads();
    }

    // Epilogue: layer-1 for the final step (TSTEPS-1)
    if (wid < mrows) {
        const int pb = (TSTEPS - 1) & 1;
        float acc = 0.0f;
#pragma unroll
        for (int k = 0; k < 8; k++)
            acc = fmaf(wi1[k], Cs[pb][wid][s1 + 8 * k], acc);
        acc += __shfl_xor_sync(0xffffffffu, acc, 4);
        acc += __shfl_xor_sync(0xffffffffu, acc, 8);
        acc += __shfl_xor_sync(0xffffffffu, acc, 16);
        acc += fmaf(whh1g, h1, b1g);
        const float gi = __shfl_sync(0xffffffffu, acc, 0);
        const float gf = __shfl_sync(0xffffffffu, acc, 1);
        const float gg = __shfl_sync(0xffffffffu, acc, 2);
        const float go = __shfl_sync(0xffffffffu, acc, 3);
        c1 = sig_f(gf) * c1 + sig_f(gi) * tanh_f(gg);
        if (lane == 0) out[(size_t)(r0 + wid) * TSTEPS + (TSTEPS - 1)] = c1;
    }
}

extern "C" void kernel_launch(void* const* d_in, const int* in_sizes, int n_in,
                              void* d_out, int out_size) {
    (void)in_sizes; (void)n_in; (void)out_size;
    lstm_kernel<<<NCTA, NTHR>>>(
        (const float*)d_in[0],  // input (2048,1024)
        (const float*)d_in[1],  // W_ih0 (256,1)
        (const float*)d_in[2],  // W_hh0 (256,64)
        (const float*)d_in[3],  // b_ih0 (256)
        (const float*)d_in[4],  // b_hh0 (256)
        (const float*)d_in[5],  // W_ih1 (4,64)
        (const float*)d_in[6],  // W_hh1 (4,1)
        (const float*)d_in[7],  // b_ih1 (4)
        (const float*)d_in[8],  // b_hh1 (4)
        (float*)d_out);         // out (2048,1024)
}